// round 1
// baseline (speedup 1.0000x reference)
#include <cuda_runtime.h>
#include <cstdint>
#include <math.h>

// Problem constants
#define B_  32
#define T_  256
#define H_  1024
#define G4  4096          // 4*H
#define K_  1024
#define M_  (B_*T_)       // 8192

// ---------------- device scratch (static globals; no allocations) ----------------
__device__ float g_x [M_*K_];        // tf32-rounded x           (32 MB)
__device__ float g_Wr[4*G4*K_];      // tf32-rounded weights: [0]=Wih0 [1]=Whh0 [2]=Wih1 [3]=Whh1 (64 MB)
__device__ float g_ih[M_*G4];        // input projection buffer  (128 MB)
__device__ float g_y1[M_*H_];        // layer-0 output (tf32-rounded, feeds layer-1 GEMM) (32 MB)
__device__ float g_hA[B_*H_];
__device__ float g_hB[B_*H_];
__device__ float g_c [B_*H_];

// ---------------- tf32 mma.sync wrapper ----------------
__device__ __forceinline__ void mma_tf32(float* c, const uint32_t* a, const uint32_t* b) {
    asm volatile(
        "mma.sync.aligned.m16n8k8.row.col.f32.tf32.tf32.f32 "
        "{%0,%1,%2,%3}, {%4,%5,%6,%7}, {%8,%9}, {%0,%1,%2,%3};\n"
        : "+f"(c[0]), "+f"(c[1]), "+f"(c[2]), "+f"(c[3])
        : "r"(a[0]), "r"(a[1]), "r"(a[2]), "r"(a[3]), "r"(b[0]), "r"(b[1]));
}

__device__ __forceinline__ float tf32r(float v) {
    uint32_t u;
    asm("cvt.rna.tf32.f32 %0, %1;" : "=r"(u) : "f"(v));
    return __uint_as_float(u);
}

// ---------------- rounding kernel: src -> tf32-rounded dst ----------------
__global__ void round_tf32_kernel(const float* __restrict__ src, int n, int dsel) {
    float* dst = (dsel == 0) ? g_x : (g_Wr + (size_t)(dsel - 1) * (G4 * K_));
    int i = blockIdx.x * blockDim.x + threadIdx.x;
    if (i < n) dst[i] = tf32r(src[i]);
}

// ---------------- input projection GEMM: g_ih = A @ W^T + bias ----------------
// A: [8192,1024] row-major (g_x or g_y1, tf32-rounded), W: [4096,1024] row-major (tf32-rounded)
#define BM 128
#define BN 128
#define BK 16
#define BKP 20

__global__ __launch_bounds__(256, 1)
void gemm_ih_kernel(int asel, int woff, const float* __restrict__ bias) {
    const float* A = asel ? g_y1 : g_x;
    const float* W = g_Wr + (size_t)woff * (G4 * K_);

    __shared__ float As[BM * BKP];
    __shared__ float Ws[BN * BKP];

    int tid  = threadIdx.x;
    int bm   = blockIdx.y * BM;
    int bn   = blockIdx.x * BN;
    int warp = tid >> 5, lane = tid & 31;
    int gid  = lane >> 2, tig = lane & 3;
    int wm   = (warp & 3) * 32;   // 0,32,64,96
    int wn   = (warp >> 2) * 64;  // 0,64

    int lrow = tid >> 2;          // 0..63
    int lcol = (tid & 3) * 4;     // 0,4,8,12
    const float* Ap0 = A + (size_t)(bm + lrow) * K_ + lcol;
    const float* Ap1 = Ap0 + (size_t)64 * K_;
    const float* Wp0 = W + (size_t)(bn + lrow) * K_ + lcol;
    const float* Wp1 = Wp0 + (size_t)64 * K_;

    float c[2][8][4];
#pragma unroll
    for (int i = 0; i < 2; i++)
#pragma unroll
        for (int j = 0; j < 8; j++)
#pragma unroll
            for (int q = 0; q < 4; q++) c[i][j][q] = 0.f;

    float4 pa0 = *(const float4*)Ap0;
    float4 pa1 = *(const float4*)Ap1;
    float4 pw0 = *(const float4*)Wp0;
    float4 pw1 = *(const float4*)Wp1;

    for (int k0 = 0; k0 < K_; k0 += BK) {
        *(float4*)&As[lrow * BKP + lcol]        = pa0;
        *(float4*)&As[(lrow + 64) * BKP + lcol] = pa1;
        *(float4*)&Ws[lrow * BKP + lcol]        = pw0;
        *(float4*)&Ws[(lrow + 64) * BKP + lcol] = pw1;
        __syncthreads();

        int kn = k0 + BK;
        if (kn < K_) {
            pa0 = *(const float4*)(Ap0 + kn);
            pa1 = *(const float4*)(Ap1 + kn);
            pw0 = *(const float4*)(Wp0 + kn);
            pw1 = *(const float4*)(Wp1 + kn);
        }

#pragma unroll
        for (int ks = 0; ks < 2; ks++) {
            int kk = ks * 8;
            uint32_t af[2][4], bf[8][2];
#pragma unroll
            for (int mi = 0; mi < 2; mi++) {
                int r = wm + mi * 16 + gid;
                af[mi][0] = __float_as_uint(As[r * BKP + kk + tig]);
                af[mi][1] = __float_as_uint(As[(r + 8) * BKP + kk + tig]);
                af[mi][2] = __float_as_uint(As[r * BKP + kk + tig + 4]);
                af[mi][3] = __float_as_uint(As[(r + 8) * BKP + kk + tig + 4]);
            }
#pragma unroll
            for (int ni = 0; ni < 8; ni++) {
                int r = wn + ni * 8 + gid;
                bf[ni][0] = __float_as_uint(Ws[r * BKP + kk + tig]);
                bf[ni][1] = __float_as_uint(Ws[r * BKP + kk + tig + 4]);
            }
#pragma unroll
            for (int mi = 0; mi < 2; mi++)
#pragma unroll
                for (int ni = 0; ni < 8; ni++)
                    mma_tf32(c[mi][ni], af[mi], bf[ni]);
        }
        __syncthreads();
    }

#pragma unroll
    for (int mi = 0; mi < 2; mi++) {
#pragma unroll
        for (int ni = 0; ni < 8; ni++) {
            int m0 = bm + wm + mi * 16 + gid;
            int n0 = bn + wn + ni * 8 + 2 * tig;
            float b0v = bias[n0], b1v = bias[n0 + 1];
            size_t o = (size_t)m0 * G4 + n0;
            g_ih[o]                      = c[mi][ni][0] + b0v;
            g_ih[o + 1]                  = c[mi][ni][1] + b1v;
            g_ih[o + (size_t)8 * G4]     = c[mi][ni][2] + b0v;
            g_ih[o + (size_t)8 * G4 + 1] = c[mi][ni][3] + b1v;
        }
    }
}

// ---------------- zero h/c ----------------
__global__ void zero_state_kernel() {
    int i = blockIdx.x * blockDim.x + threadIdx.x;
    if (i < B_ * H_) { g_hA[i] = 0.f; g_hB[i] = 0.f; g_c[i] = 0.f; }
}

// ---------------- fused recurrent step: pre = ih_t + h@Whh^T, gates, c/h update ----------------
// grid = 128 blocks; block owns j in [j0, j0+8) => 32 gathered N-cols {g*1024 + j0 + jj}
#define SBK 32
#define SBKP 36

__global__ __launch_bounds__(256, 1)
void lstm_step_kernel(int t, int parity, int whoff, int outsel, float* out_ext) {
    const float* hin  = parity ? g_hB : g_hA;
    float*       hout = parity ? g_hA : g_hB;
    float*       out  = outsel ? out_ext : g_y1;
    const float* W    = g_Wr + (size_t)whoff * (G4 * K_);
    int j0 = blockIdx.x * 8;

    __shared__ float Hs [32 * SBKP];
    __shared__ float Ws2[32 * SBKP];
    __shared__ float Ps [32 * 33];

    int tid  = threadIdx.x;
    int warp = tid >> 5, lane = tid & 31;
    int gid  = lane >> 2, tig = lane & 3;
    int mi   = warp & 1;    // m16 tile: batches [mi*16, mi*16+16)
    int ni   = warp >> 1;   // n8 tile: cols [ni*8, ni*8+8)

    int lrow = tid >> 3;        // 0..31
    int lcol = (tid & 7) * 4;   // 0..28
    int wrow = (lrow >> 3) * H_ + j0 + (lrow & 7);   // gathered Whh row: gate*H + j
    const float* Hp = hin + lrow * H_ + lcol;
    const float* Wp = W + (size_t)wrow * K_ + lcol;

    float c[4] = {0.f, 0.f, 0.f, 0.f};
    float4 ph = *(const float4*)Hp;
    float4 pw = *(const float4*)Wp;

    for (int k0 = 0; k0 < K_; k0 += SBK) {
        *(float4*)&Hs [lrow * SBKP + lcol] = ph;
        *(float4*)&Ws2[lrow * SBKP + lcol] = pw;
        __syncthreads();
        int kn = k0 + SBK;
        if (kn < K_) {
            ph = *(const float4*)(Hp + kn);
            pw = *(const float4*)(Wp + kn);
        }
#pragma unroll
        for (int ks = 0; ks < 4; ks++) {
            int kk = ks * 8;
            uint32_t af[4], bf[2];
            int r = mi * 16 + gid;
            af[0] = __float_as_uint(Hs[r * SBKP + kk + tig]);
            af[1] = __float_as_uint(Hs[(r + 8) * SBKP + kk + tig]);
            af[2] = __float_as_uint(Hs[r * SBKP + kk + tig + 4]);
            af[3] = __float_as_uint(Hs[(r + 8) * SBKP + kk + tig + 4]);
            int rn = ni * 8 + gid;
            bf[0] = __float_as_uint(Ws2[rn * SBKP + kk + tig]);
            bf[1] = __float_as_uint(Ws2[rn * SBKP + kk + tig + 4]);
            mma_tf32(c, af, bf);
        }
        __syncthreads();
    }

    // scatter pre-activations to smem so each thread can gather its 4 gates
    {
        int m = mi * 16 + gid;
        int n = ni * 8 + 2 * tig;
        Ps[m * 33 + n]           = c[0];
        Ps[m * 33 + n + 1]       = c[1];
        Ps[(m + 8) * 33 + n]     = c[2];
        Ps[(m + 8) * 33 + n + 1] = c[3];
    }
    __syncthreads();

    // gate math: one (b, j) per thread
    {
        int b  = tid >> 3;   // 0..31
        int jj = tid & 7;
        size_t ihbase = ((size_t)(b * T_ + t)) * G4 + j0 + jj;
        float ipre = Ps[b * 33 + jj]          + g_ih[ihbase];
        float fpre = Ps[b * 33 + 8 + jj]      + g_ih[ihbase + H_];
        float gpre = Ps[b * 33 + 16 + jj]     + g_ih[ihbase + 2 * H_];
        float opre = Ps[b * 33 + 24 + jj]     + g_ih[ihbase + 3 * H_];
        float iv = 1.f / (1.f + __expf(-ipre));
        float fv = 1.f / (1.f + __expf(-fpre));
        float gv = tanhf(gpre);
        float ov = 1.f / (1.f + __expf(-opre));
        int cidx = b * H_ + j0 + jj;
        float cn = fv * g_c[cidx] + iv * gv;
        g_c[cidx] = cn;
        float hv = ov * tanhf(cn);
        float hr = tf32r(hv);           // rounded copy feeds next step's mma
        hout[cidx] = hr;
        size_t oidx = ((size_t)(b * T_ + t)) * H_ + j0 + jj;
        out[oidx] = outsel ? hv : hr;   // layer-0 output feeds a GEMM -> keep it tf32-rounded
    }
}

// ---------------- launch ----------------
extern "C" void kernel_launch(void* const* d_in, const int* in_sizes, int n_in,
                              void* d_out, int out_size) {
    const float* x    = (const float*)d_in[0];
    const float* Wih0 = (const float*)d_in[1];
    const float* Whh0 = (const float*)d_in[2];
    const float* b0   = (const float*)d_in[3];
    const float* Wih1 = (const float*)d_in[4];
    const float* Whh1 = (const float*)d_in[5];
    const float* b1   = (const float*)d_in[6];
    float* out = (float*)d_out;

    const int nx = M_ * K_;   // 8388608
    const int nw = G4 * K_;   // 4194304
    round_tf32_kernel<<<(nx + 255) / 256, 256>>>(x,    nx, 0);
    round_tf32_kernel<<<(nw + 255) / 256, 256>>>(Wih0, nw, 1);
    round_tf32_kernel<<<(nw + 255) / 256, 256>>>(Whh0, nw, 2);
    round_tf32_kernel<<<(nw + 255) / 256, 256>>>(Wih1, nw, 3);
    round_tf32_kernel<<<(nw + 255) / 256, 256>>>(Whh1, nw, 4);

    dim3 ggrid(G4 / BN, M_ / BM);   // (32, 64)

    // layer 0
    gemm_ih_kernel<<<ggrid, 256>>>(0, 0, b0);
    zero_state_kernel<<<(B_ * H_ + 1023) / 1024, 1024>>>();
    for (int t = 0; t < T_; t++)
        lstm_step_kernel<<<H_ / 8, 256>>>(t, t & 1, 1, 0, nullptr);

    // layer 1
    gemm_ih_kernel<<<ggrid, 256>>>(1, 2, b1);
    zero_state_kernel<<<(B_ * H_ + 1023) / 1024, 1024>>>();
    for (int t = 0; t < T_; t++)
        lstm_step_kernel<<<H_ / 8, 256>>>(t, t & 1, 3, 1, out);
}

// round 2
// speedup vs baseline: 1.5046x; 1.5046x over previous
#include <cuda_runtime.h>
#include <cstdint>
#include <math.h>

// Problem constants
#define B_  32
#define T_  256
#define H_  1024
#define G4  4096          // 4*H
#define K_  1024
#define M_  (B_*T_)       // 8192
#define NCTA 128

// ---------------- device scratch (static globals; no allocations) ----------------
__device__ float g_x [M_*K_];        // tf32-rounded x
__device__ float g_Wr[2*G4*K_];      // tf32-rounded Wih0, Wih1
__device__ float g_ih[M_*G4];        // input projection buffer
__device__ float g_y1[M_*H_];        // layer-0 output (tf32-rounded)
__device__ float g_hA[B_*H_];
__device__ float g_hB[B_*H_];
__device__ unsigned g_bar;

// ---------------- tf32 mma.sync wrapper ----------------
__device__ __forceinline__ void mma_tf32(float* c, const uint32_t* a, const uint32_t* b) {
    asm volatile(
        "mma.sync.aligned.m16n8k8.row.col.f32.tf32.tf32.f32 "
        "{%0,%1,%2,%3}, {%4,%5,%6,%7}, {%8,%9}, {%0,%1,%2,%3};\n"
        : "+f"(c[0]), "+f"(c[1]), "+f"(c[2]), "+f"(c[3])
        : "r"(a[0]), "r"(a[1]), "r"(a[2]), "r"(a[3]), "r"(b[0]), "r"(b[1]));
}

__device__ __forceinline__ float tf32r(float v) {
    uint32_t u;
    asm("cvt.rna.tf32.f32 %0, %1;" : "=r"(u) : "f"(v));
    return __uint_as_float(u);
}

// ---------------- rounding kernel ----------------
__global__ void round_tf32_kernel(const float* __restrict__ src, int n, int dsel) {
    float* dst = (dsel == 0) ? g_x : (g_Wr + (size_t)(dsel - 1) * (G4 * K_));
    int i = blockIdx.x * blockDim.x + threadIdx.x;
    if (i < n) dst[i] = tf32r(src[i]);
}

// ---------------- input projection GEMM: g_ih = A @ W^T + bias ----------------
#define BM 128
#define BN 128
#define BK 16
#define BKP 20

__global__ __launch_bounds__(256, 1)
void gemm_ih_kernel(int asel, int woff, const float* __restrict__ bias) {
    const float* A = asel ? g_y1 : g_x;
    const float* W = g_Wr + (size_t)woff * (G4 * K_);

    __shared__ float As[BM * BKP];
    __shared__ float Ws[BN * BKP];

    int tid  = threadIdx.x;
    int bm   = blockIdx.y * BM;
    int bn   = blockIdx.x * BN;
    int warp = tid >> 5, lane = tid & 31;
    int gid  = lane >> 2, tig = lane & 3;
    int wm   = (warp & 3) * 32;
    int wn   = (warp >> 2) * 64;

    int lrow = tid >> 2;
    int lcol = (tid & 3) * 4;
    const float* Ap0 = A + (size_t)(bm + lrow) * K_ + lcol;
    const float* Ap1 = Ap0 + (size_t)64 * K_;
    const float* Wp0 = W + (size_t)(bn + lrow) * K_ + lcol;
    const float* Wp1 = Wp0 + (size_t)64 * K_;

    float c[2][8][4];
#pragma unroll
    for (int i = 0; i < 2; i++)
#pragma unroll
        for (int j = 0; j < 8; j++)
#pragma unroll
            for (int q = 0; q < 4; q++) c[i][j][q] = 0.f;

    float4 pa0 = *(const float4*)Ap0;
    float4 pa1 = *(const float4*)Ap1;
    float4 pw0 = *(const float4*)Wp0;
    float4 pw1 = *(const float4*)Wp1;

    for (int k0 = 0; k0 < K_; k0 += BK) {
        *(float4*)&As[lrow * BKP + lcol]        = pa0;
        *(float4*)&As[(lrow + 64) * BKP + lcol] = pa1;
        *(float4*)&Ws[lrow * BKP + lcol]        = pw0;
        *(float4*)&Ws[(lrow + 64) * BKP + lcol] = pw1;
        __syncthreads();

        int kn = k0 + BK;
        if (kn < K_) {
            pa0 = *(const float4*)(Ap0 + kn);
            pa1 = *(const float4*)(Ap1 + kn);
            pw0 = *(const float4*)(Wp0 + kn);
            pw1 = *(const float4*)(Wp1 + kn);
        }

#pragma unroll
        for (int ks = 0; ks < 2; ks++) {
            int kk = ks * 8;
            uint32_t af[2][4], bf[8][2];
#pragma unroll
            for (int mi = 0; mi < 2; mi++) {
                int r = wm + mi * 16 + gid;
                af[mi][0] = __float_as_uint(As[r * BKP + kk + tig]);
                af[mi][1] = __float_as_uint(As[(r + 8) * BKP + kk + tig]);
                af[mi][2] = __float_as_uint(As[r * BKP + kk + tig + 4]);
                af[mi][3] = __float_as_uint(As[(r + 8) * BKP + kk + tig + 4]);
            }
#pragma unroll
            for (int ni = 0; ni < 8; ni++) {
                int r = wn + ni * 8 + gid;
                bf[ni][0] = __float_as_uint(Ws[r * BKP + kk + tig]);
                bf[ni][1] = __float_as_uint(Ws[r * BKP + kk + tig + 4]);
            }
#pragma unroll
            for (int mi = 0; mi < 2; mi++)
#pragma unroll
                for (int ni = 0; ni < 8; ni++)
                    mma_tf32(c[mi][ni], af[mi], bf[ni]);
        }
        __syncthreads();
    }

#pragma unroll
    for (int mi = 0; mi < 2; mi++) {
#pragma unroll
        for (int ni = 0; ni < 8; ni++) {
            int m0 = bm + wm + mi * 16 + gid;
            int n0 = bn + wn + ni * 8 + 2 * tig;
            float b0v = bias[n0], b1v = bias[n0 + 1];
            size_t o = (size_t)m0 * G4 + n0;
            g_ih[o]                      = c[mi][ni][0] + b0v;
            g_ih[o + 1]                  = c[mi][ni][1] + b1v;
            g_ih[o + (size_t)8 * G4]     = c[mi][ni][2] + b0v;
            g_ih[o + (size_t)8 * G4 + 1] = c[mi][ni][3] + b1v;
        }
    }
}

// ---------------- zero h / barrier ----------------
__global__ void zero_state_kernel() {
    int i = blockIdx.x * blockDim.x + threadIdx.x;
    if (i < B_ * H_) { g_hA[i] = 0.f; g_hB[i] = 0.f; }
    if (i == 0) g_bar = 0u;
}

// ---------------- persistent recurrence kernel ----------------
// 128 CTAs, 1 per SM (169.6 KB smem). CTA owns j in [j0, j0+8) -> 32 gathered
// Whh rows resident in SMEM for all 256 steps. Grid barrier between steps.
#define CHUNK 128
#define HS_STRIDE 132
#define WS_STRIDE 1028
#define PERSIST_SMEM ((32*WS_STRIDE + 2*32*HS_STRIDE + 32*33) * 4)

__global__ __launch_bounds__(256, 1)
void lstm_persist_kernel(const float* __restrict__ Whh_raw, int outsel,
                         float* __restrict__ out_ext)
{
    extern __shared__ float sm[];
    float* Ws = sm;                              // 32 x 1028
    float* Hs = Ws + 32 * WS_STRIDE;             // 2 x 32 x 132
    float* Ps = Hs + 2 * 32 * HS_STRIDE;         // 32 x 33

    int tid  = threadIdx.x;
    int warp = tid >> 5, lane = tid & 31;
    int gid  = lane >> 2, tig = lane & 3;
    int mi   = warp & 1;     // m16 tile
    int ni   = warp >> 1;    // n8 tile
    int j0   = blockIdx.x * 8;

    // ---- load Whh slice into SMEM once, tf32-rounded (gathered gate layout) ----
#pragma unroll 4
    for (int i = 0; i < 32; i++) {
        int idx = i * 256 + tid;             // 0..8191
        int r   = idx >> 8;                  // smem row 0..31
        int c4  = idx & 255;                 // float4 col
        int g   = r >> 3, jr = r & 7;
        const float4 v = *(const float4*)(Whh_raw + ((size_t)(g * H_ + j0 + jr)) * K_ + c4 * 4);
        float4 w;
        w.x = tf32r(v.x); w.y = tf32r(v.y); w.z = tf32r(v.z); w.w = tf32r(v.w);
        *(float4*)&Ws[r * WS_STRIDE + c4 * 4] = w;
    }

    int b  = tid >> 3;       // gate-math identity: batch
    int jj = tid & 7;        // hidden col within slice
    float c_state = 0.f;     // cell state lives in a register
    float* outp = outsel ? out_ext : g_y1;

    __syncthreads();

    for (int t = 0; t < T_; t++) {
        const float* hin  = (t & 1) ? g_hB : g_hA;
        float*       hout = (t & 1) ? g_hA : g_hB;

        float accA[4] = {0.f, 0.f, 0.f, 0.f};
        float accB[4] = {0.f, 0.f, 0.f, 0.f};

        // prologue: load chunk 0 of h into regs
        float4 ra[4];
        {
            int r0 = tid >> 5, c0 = (tid & 31) * 4;
#pragma unroll
            for (int p = 0; p < 4; p++)
                ra[p] = __ldcg((const float4*)(hin + (size_t)(r0 + 8 * p) * K_ + c0));
        }

        for (int kc = 0; kc < 8; kc++) {
            float* hb = Hs + (kc & 1) * 32 * HS_STRIDE;
            {
                int r0 = tid >> 5, c0 = (tid & 31) * 4;
#pragma unroll
                for (int p = 0; p < 4; p++)
                    *(float4*)&hb[(r0 + 8 * p) * HS_STRIDE + c0] = ra[p];
            }
            __syncthreads();
            if (kc < 7) {
                int r0 = tid >> 5, c0 = (tid & 31) * 4;
                const float* base = hin + (kc + 1) * CHUNK;
#pragma unroll
                for (int p = 0; p < 4; p++)
                    ra[p] = __ldcg((const float4*)(base + (size_t)(r0 + 8 * p) * K_ + c0));
            }
            int kw = kc * CHUNK;
#pragma unroll
            for (int ks = 0; ks < 16; ks++) {
                int kk = ks * 8;
                uint32_t af[4], bf[2];
                int r = mi * 16 + gid;
                af[0] = __float_as_uint(hb[r * HS_STRIDE + kk + tig]);
                af[1] = __float_as_uint(hb[(r + 8) * HS_STRIDE + kk + tig]);
                af[2] = __float_as_uint(hb[r * HS_STRIDE + kk + tig + 4]);
                af[3] = __float_as_uint(hb[(r + 8) * HS_STRIDE + kk + tig + 4]);
                int rn = ni * 8 + gid;
                bf[0] = __float_as_uint(Ws[rn * WS_STRIDE + kw + kk + tig]);
                bf[1] = __float_as_uint(Ws[rn * WS_STRIDE + kw + kk + tig + 4]);
                mma_tf32((ks & 1) ? accB : accA, af, bf);
            }
        }

        // scatter pre-activations so each thread can gather its 4 gates
        {
            int m = mi * 16 + gid;
            int n = ni * 8 + 2 * tig;
            Ps[m * 33 + n]           = accA[0] + accB[0];
            Ps[m * 33 + n + 1]       = accA[1] + accB[1];
            Ps[(m + 8) * 33 + n]     = accA[2] + accB[2];
            Ps[(m + 8) * 33 + n + 1] = accA[3] + accB[3];
        }
        __syncthreads();

        // gate math: one (b, jj) per thread
        {
            size_t ihbase = ((size_t)(b * T_ + t)) * G4 + j0 + jj;
            float ipre = Ps[b * 33 + jj]      + __ldcs(&g_ih[ihbase]);
            float fpre = Ps[b * 33 + 8 + jj]  + __ldcs(&g_ih[ihbase + H_]);
            float gpre = Ps[b * 33 + 16 + jj] + __ldcs(&g_ih[ihbase + 2 * H_]);
            float opre = Ps[b * 33 + 24 + jj] + __ldcs(&g_ih[ihbase + 3 * H_]);
            float iv = 1.f / (1.f + __expf(-ipre));
            float fv = 1.f / (1.f + __expf(-fpre));
            float gv = tanhf(gpre);
            float ov = 1.f / (1.f + __expf(-opre));
            c_state = fv * c_state + iv * gv;
            float hv = ov * tanhf(c_state);
            float hr = tf32r(hv);                 // rounded copy feeds next step's mma
            __stcg(&hout[b * H_ + j0 + jj], hr);
            size_t oidx = ((size_t)(b * T_ + t)) * H_ + j0 + jj;
            outp[oidx] = outsel ? hv : hr;        // layer-0 output feeds a GEMM -> tf32-rounded
        }

        // ---- grid barrier ----
        __threadfence();
        __syncthreads();
        if (tid == 0) {
            atomicAdd(&g_bar, 1u);
            unsigned target = (unsigned)NCTA * (unsigned)(t + 1);
            unsigned v;
            do {
                asm volatile("ld.acquire.gpu.global.u32 %0, [%1];" : "=r"(v) : "l"(&g_bar));
            } while (v < target);
        }
        __syncthreads();
    }
}

// ---------------- launch ----------------
extern "C" void kernel_launch(void* const* d_in, const int* in_sizes, int n_in,
                              void* d_out, int out_size) {
    const float* x    = (const float*)d_in[0];
    const float* Wih0 = (const float*)d_in[1];
    const float* Whh0 = (const float*)d_in[2];
    const float* b0   = (const float*)d_in[3];
    const float* Wih1 = (const float*)d_in[4];
    const float* Whh1 = (const float*)d_in[5];
    const float* b1   = (const float*)d_in[6];
    float* out = (float*)d_out;

    static int smem_set = 0;
    if (!smem_set) {
        cudaFuncSetAttribute(lstm_persist_kernel,
                             cudaFuncAttributeMaxDynamicSharedMemorySize, PERSIST_SMEM);
        smem_set = 1;
    }

    const int nx = M_ * K_;
    const int nw = G4 * K_;
    round_tf32_kernel<<<(nx + 255) / 256, 256>>>(x,    nx, 0);
    round_tf32_kernel<<<(nw + 255) / 256, 256>>>(Wih0, nw, 1);
    round_tf32_kernel<<<(nw + 255) / 256, 256>>>(Wih1, nw, 2);

    dim3 ggrid(G4 / BN, M_ / BM);   // (32, 64)

    // layer 0
    gemm_ih_kernel<<<ggrid, 256>>>(0, 0, b0);
    zero_state_kernel<<<(B_ * H_ + 1023) / 1024, 1024>>>();
    lstm_persist_kernel<<<NCTA, 256, PERSIST_SMEM>>>(Whh0, 0, nullptr);

    // layer 1
    gemm_ih_kernel<<<ggrid, 256>>>(1, 1, b1);
    zero_state_kernel<<<(B_ * H_ + 1023) / 1024, 1024>>>();
    lstm_persist_kernel<<<NCTA, 256, PERSIST_SMEM>>>(Whh1, 1, out);
}

// round 3
// speedup vs baseline: 2.6229x; 1.7432x over previous
#include <cuda_runtime.h>
#include <cuda_fp16.h>
#include <cstdint>
#include <math.h>

// Problem constants
#define B_  32
#define T_  256
#define H_  1024
#define G4  4096
#define K_  1024
#define M_  (B_*T_)       // 8192
#define NCTA 128

// ---------------- device scratch ----------------
__device__ __half g_xh [M_*K_];       // fp16 x
__device__ __half g_Wh [2*G4*K_];     // fp16 Wih0, Wih1
__device__ float  g_ih [M_*G4];       // input projection (fp32)
__device__ __half g_y1h[M_*H_];       // layer-0 output (fp16, feeds layer-1 GEMM)
__device__ __half g_hA [B_*H_];
__device__ __half g_hB [B_*H_];
__device__ unsigned g_bar;

// ---------------- fp16 mma wrapper ----------------
__device__ __forceinline__ void mma_f16(float* c, const uint32_t* a, const uint32_t* b) {
    asm volatile(
        "mma.sync.aligned.m16n8k16.row.col.f32.f16.f16.f32 "
        "{%0,%1,%2,%3}, {%4,%5,%6,%7}, {%8,%9}, {%0,%1,%2,%3};\n"
        : "+f"(c[0]), "+f"(c[1]), "+f"(c[2]), "+f"(c[3])
        : "r"(a[0]), "r"(a[1]), "r"(a[2]), "r"(a[3]), "r"(b[0]), "r"(b[1]));
}

// ---------------- fp32 -> fp16 conversion ----------------
__global__ void round_half_kernel(const float* __restrict__ src, int n, int dsel) {
    __half* dst = (dsel == 0) ? g_xh : (g_Wh + (size_t)(dsel - 1) * (G4 * K_));
    int i4 = (blockIdx.x * blockDim.x + threadIdx.x) * 4;
    if (i4 < n) {
        float4 v = *(const float4*)(src + i4);
        *(__half2*)(dst + i4)     = __floats2half2_rn(v.x, v.y);
        *(__half2*)(dst + i4 + 2) = __floats2half2_rn(v.z, v.w);
    }
}

// ---------------- input projection GEMM (fp16): g_ih = A @ W^T + bias ----------------
#define BM 128
#define BN 128
#define BKH 32     // halves per k-iter
#define GSTR 40    // smem row stride in halves

__global__ __launch_bounds__(256, 1)
void gemm_ih_kernel(int asel, int woff, const float* __restrict__ bias) {
    const __half* A = asel ? g_y1h : g_xh;
    const __half* W = g_Wh + (size_t)woff * (G4 * K_);

    __shared__ __half As[BM * GSTR];
    __shared__ __half Bs[BN * GSTR];

    int tid  = threadIdx.x;
    int bm   = blockIdx.y * BM;
    int bn   = blockIdx.x * BN;
    int warp = tid >> 5, lane = tid & 31;
    int gid  = lane >> 2, tig = lane & 3;
    int wm   = (warp & 3) * 32;
    int wn   = (warp >> 2) * 64;

    int r0 = tid >> 2;            // 0..63
    int c8 = (tid & 3) * 8;       // halves
    const __half* Ap0 = A + (size_t)(bm + r0) * K_ + c8;
    const __half* Ap1 = Ap0 + (size_t)64 * K_;
    const __half* Wp0 = W + (size_t)(bn + r0) * K_ + c8;
    const __half* Wp1 = Wp0 + (size_t)64 * K_;

    float c[2][8][4];
#pragma unroll
    for (int i = 0; i < 2; i++)
#pragma unroll
        for (int j = 0; j < 8; j++)
#pragma unroll
            for (int q = 0; q < 4; q++) c[i][j][q] = 0.f;

    uint4 pa0 = *(const uint4*)Ap0;
    uint4 pa1 = *(const uint4*)Ap1;
    uint4 pw0 = *(const uint4*)Wp0;
    uint4 pw1 = *(const uint4*)Wp1;

    for (int k0 = 0; k0 < K_; k0 += BKH) {
        *(uint4*)&As[r0 * GSTR + c8]        = pa0;
        *(uint4*)&As[(r0 + 64) * GSTR + c8] = pa1;
        *(uint4*)&Bs[r0 * GSTR + c8]        = pw0;
        *(uint4*)&Bs[(r0 + 64) * GSTR + c8] = pw1;
        __syncthreads();

        int kn = k0 + BKH;
        if (kn < K_) {
            pa0 = *(const uint4*)(Ap0 + kn);
            pa1 = *(const uint4*)(Ap1 + kn);
            pw0 = *(const uint4*)(Wp0 + kn);
            pw1 = *(const uint4*)(Wp1 + kn);
        }

#pragma unroll
        for (int ks = 0; ks < 2; ks++) {
            int kk = ks * 16;
            uint32_t af[2][4], bf[8][2];
#pragma unroll
            for (int mi = 0; mi < 2; mi++) {
                int r = wm + mi * 16 + gid;
                af[mi][0] = *(const uint32_t*)&As[r * GSTR + kk + 2 * tig];
                af[mi][1] = *(const uint32_t*)&As[(r + 8) * GSTR + kk + 2 * tig];
                af[mi][2] = *(const uint32_t*)&As[r * GSTR + kk + 8 + 2 * tig];
                af[mi][3] = *(const uint32_t*)&As[(r + 8) * GSTR + kk + 8 + 2 * tig];
            }
#pragma unroll
            for (int ni = 0; ni < 8; ni++) {
                int r = wn + ni * 8 + gid;
                bf[ni][0] = *(const uint32_t*)&Bs[r * GSTR + kk + 2 * tig];
                bf[ni][1] = *(const uint32_t*)&Bs[r * GSTR + kk + 8 + 2 * tig];
            }
#pragma unroll
            for (int mi = 0; mi < 2; mi++)
#pragma unroll
                for (int ni = 0; ni < 8; ni++)
                    mma_f16(c[mi][ni], af[mi], bf[ni]);
        }
        __syncthreads();
    }

#pragma unroll
    for (int mi = 0; mi < 2; mi++) {
#pragma unroll
        for (int ni = 0; ni < 8; ni++) {
            int m0 = bm + wm + mi * 16 + gid;
            int n0 = bn + wn + ni * 8 + 2 * tig;
            float b0v = bias[n0], b1v = bias[n0 + 1];
            size_t o = (size_t)m0 * G4 + n0;
            g_ih[o]                      = c[mi][ni][0] + b0v;
            g_ih[o + 1]                  = c[mi][ni][1] + b1v;
            g_ih[o + (size_t)8 * G4]     = c[mi][ni][2] + b0v;
            g_ih[o + (size_t)8 * G4 + 1] = c[mi][ni][3] + b1v;
        }
    }
}

// ---------------- zero h / barrier ----------------
__global__ void zero_state_kernel() {
    int i = blockIdx.x * blockDim.x + threadIdx.x;
    if (i < B_ * H_) {
        g_hA[i] = __float2half(0.f);
        g_hB[i] = __float2half(0.f);
    }
    if (i == 0) g_bar = 0u;
}

// ---------------- persistent recurrence kernel (fp16 + ldmatrix) ----------------
#define CHUNKH 256                 // halves of h per chunk
#define HSTR 264                   // Hs row stride (halves)
#define WSTR 1032                  // Ws row stride (halves)
#define PERSIST_SMEM (32*WSTR*2 + 2*32*HSTR*2 + 32*33*4)

__global__ __launch_bounds__(256, 1)
void lstm_persist_kernel(const float* __restrict__ Whh_raw, int outsel,
                         float* __restrict__ out_ext)
{
    extern __shared__ __half smh[];
    __half* Wsm = smh;                               // 32 x 1032 halves
    __half* Hsm = Wsm + 32 * WSTR;                   // 2 x 32 x 264 halves
    float*  Ps  = (float*)(Hsm + 2 * 32 * HSTR);     // 32 x 33 floats

    int tid  = threadIdx.x;
    int warp = tid >> 5, lane = tid & 31;
    int gid  = lane >> 2, tig = lane & 3;
    int mi   = warp & 1;     // m16 tile (batches)
    int ni   = warp >> 1;    // n8 tile (gathered cols)
    int j0   = blockIdx.x * 8;

    // ---- load Whh slice into SMEM once (fp16, gathered gate layout) ----
#pragma unroll 4
    for (int i = 0; i < 32; i++) {
        int idx = i * 256 + tid;
        int r   = idx >> 8;              // 0..31
        int c4  = idx & 255;             // float4 col
        int g   = r >> 3, jr = r & 7;
        const float4 v = *(const float4*)(Whh_raw + ((size_t)(g * H_ + j0 + jr)) * K_ + c4 * 4);
        *(__half2*)&Wsm[r * WSTR + c4 * 4]     = __floats2half2_rn(v.x, v.y);
        *(__half2*)&Wsm[r * WSTR + c4 * 4 + 2] = __floats2half2_rn(v.z, v.w);
    }

    // ---- ldmatrix per-lane address precompute ----
    uint32_t hs_base = (uint32_t)__cvta_generic_to_shared(Hsm);
    uint32_t ws_base = (uint32_t)__cvta_generic_to_shared(Wsm);
    int row_a = mi * 16 + (lane & 7) + ((lane >> 3) & 1) * 8;
    int kof_a = (lane >> 4) * 8;
    uint32_t a_off = (uint32_t)(row_a * HSTR + kof_a) * 2;
    int lb    = lane & 15;
    int row_b = ni * 8 + (lb & 7);
    int kof_b = ((lb >> 3) & 1) * 8;
    uint32_t b_base = ws_base + (uint32_t)(row_b * WSTR + kof_b) * 2;

    int hrow = tid >> 5;          // 0..7 (plus +8p)
    int hc   = (lane) * 8;        // halves within chunk
    int b    = tid >> 3;          // gate-math: batch
    int jj   = tid & 7;           // hidden col within slice
    float c_state = 0.f;

    __syncthreads();

    for (int t = 0; t < T_; t++) {
        const __half* hin  = (t & 1) ? g_hB : g_hA;
        __half*       hout = (t & 1) ? g_hA : g_hB;

        // prefetch ih gate operands (overlaps with mma work below)
        size_t ihbase = ((size_t)(b * T_ + t)) * G4 + j0 + jj;
        float ih0 = __ldcs(&g_ih[ihbase]);
        float ih1 = __ldcs(&g_ih[ihbase + H_]);
        float ih2 = __ldcs(&g_ih[ihbase + 2 * H_]);
        float ih3 = __ldcs(&g_ih[ihbase + 3 * H_]);

        float accA[4] = {0.f, 0.f, 0.f, 0.f};
        float accB[4] = {0.f, 0.f, 0.f, 0.f};

        // prologue: load chunk 0 of h
        uint4 ra[4];
#pragma unroll
        for (int p = 0; p < 4; p++)
            ra[p] = __ldcg((const uint4*)(hin + (size_t)(hrow + 8 * p) * H_ + hc));

        for (int kc = 0; kc < 4; kc++) {
            __half* hb = Hsm + (kc & 1) * 32 * HSTR;
#pragma unroll
            for (int p = 0; p < 4; p++)
                *(uint4*)&hb[(hrow + 8 * p) * HSTR + hc] = ra[p];
            __syncthreads();
            if (kc < 3) {
                const __half* base = hin + (kc + 1) * CHUNKH;
#pragma unroll
                for (int p = 0; p < 4; p++)
                    ra[p] = __ldcg((const uint4*)(base + (size_t)(hrow + 8 * p) * H_ + hc));
            }
            uint32_t aaddr = hs_base + (kc & 1) * (32 * HSTR * 2) + a_off;
            uint32_t baddr = b_base + (uint32_t)(kc * CHUNKH) * 2;
#pragma unroll
            for (int ks = 0; ks < 16; ks++) {
                uint32_t a0, a1, a2, a3, b0v, b1v;
                asm volatile("ldmatrix.sync.aligned.m8n8.x4.shared.b16 {%0,%1,%2,%3}, [%4];"
                             : "=r"(a0), "=r"(a1), "=r"(a2), "=r"(a3) : "r"(aaddr));
                asm volatile("ldmatrix.sync.aligned.m8n8.x2.shared.b16 {%0,%1}, [%2];"
                             : "=r"(b0v), "=r"(b1v) : "r"(baddr));
                uint32_t af[4] = {a0, a1, a2, a3};
                uint32_t bf[2] = {b0v, b1v};
                mma_f16((ks & 1) ? accB : accA, af, bf);
                aaddr += 32;
                baddr += 32;
            }
        }

        // scatter pre-activations so each thread can gather its 4 gates
        {
            int m = mi * 16 + gid;
            int n = ni * 8 + 2 * tig;
            Ps[m * 33 + n]           = accA[0] + accB[0];
            Ps[m * 33 + n + 1]       = accA[1] + accB[1];
            Ps[(m + 8) * 33 + n]     = accA[2] + accB[2];
            Ps[(m + 8) * 33 + n + 1] = accA[3] + accB[3];
        }
        __syncthreads();

        // gate math: one (b, jj) per thread
        {
            float ipre = Ps[b * 33 + jj]      + ih0;
            float fpre = Ps[b * 33 + 8 + jj]  + ih1;
            float gpre = Ps[b * 33 + 16 + jj] + ih2;
            float opre = Ps[b * 33 + 24 + jj] + ih3;
            float iv = 1.f / (1.f + __expf(-ipre));
            float fv = 1.f / (1.f + __expf(-fpre));
            float gv = tanhf(gpre);
            float ov = 1.f / (1.f + __expf(-opre));
            c_state = fv * c_state + iv * gv;
            float hv = ov * tanhf(c_state);
            __half hr = __float2half_rn(hv);
            unsigned short hb16 = __half_as_ushort(hr);
            asm volatile("st.global.cg.u16 [%0], %1;"
                         :: "l"(hout + b * H_ + j0 + jj), "h"(hb16) : "memory");
            size_t oidx = ((size_t)(b * T_ + t)) * H_ + j0 + jj;
            if (outsel) out_ext[oidx] = hv;
            else        g_y1h[oidx]   = hr;     // feeds layer-1 GEMM (fp16)
        }

        // ---- grid barrier ----
        __threadfence();
        __syncthreads();
        if (tid == 0) {
            atomicAdd(&g_bar, 1u);
            unsigned target = (unsigned)NCTA * (unsigned)(t + 1);
            unsigned v;
            do {
                asm volatile("ld.acquire.gpu.global.u32 %0, [%1];" : "=r"(v) : "l"(&g_bar));
            } while (v < target);
        }
        __syncthreads();
    }
}

// ---------------- launch ----------------
extern "C" void kernel_launch(void* const* d_in, const int* in_sizes, int n_in,
                              void* d_out, int out_size) {
    const float* x    = (const float*)d_in[0];
    const float* Wih0 = (const float*)d_in[1];
    const float* Whh0 = (const float*)d_in[2];
    const float* b0   = (const float*)d_in[3];
    const float* Wih1 = (const float*)d_in[4];
    const float* Whh1 = (const float*)d_in[5];
    const float* b1   = (const float*)d_in[6];
    float* out = (float*)d_out;

    static int smem_set = 0;
    if (!smem_set) {
        cudaFuncSetAttribute(lstm_persist_kernel,
                             cudaFuncAttributeMaxDynamicSharedMemorySize, PERSIST_SMEM);
        smem_set = 1;
    }

    const int nx = M_ * K_;
    const int nw = G4 * K_;
    round_half_kernel<<<(nx / 4 + 255) / 256, 256>>>(x,    nx, 0);
    round_half_kernel<<<(nw / 4 + 255) / 256, 256>>>(Wih0, nw, 1);
    round_half_kernel<<<(nw / 4 + 255) / 256, 256>>>(Wih1, nw, 2);

    dim3 ggrid(G4 / BN, M_ / BM);   // (32, 64)

    // layer 0
    gemm_ih_kernel<<<ggrid, 256>>>(0, 0, b0);
    zero_state_kernel<<<(B_ * H_ + 1023) / 1024, 1024>>>();
    lstm_persist_kernel<<<NCTA, 256, PERSIST_SMEM>>>(Whh0, 0, nullptr);

    // layer 1
    gemm_ih_kernel<<<ggrid, 256>>>(1, 1, b1);
    zero_state_kernel<<<(B_ * H_ + 1023) / 1024, 1024>>>();
    lstm_persist_kernel<<<NCTA, 256, PERSIST_SMEM>>>(Whh1, 1, out);
}

// round 4
// speedup vs baseline: 3.0385x; 1.1585x over previous
#include <cuda_runtime.h>
#include <cuda_fp16.h>
#include <cstdint>
#include <math.h>

// Problem constants
#define B_  32
#define T_  256
#define H_  1024
#define G4  4096
#define K_  1024
#define M_  (B_*T_)       // 8192
#define NCTA 128

// ---------------- device scratch ----------------
__device__ __half g_xh [M_*K_];       // fp16 x
__device__ __half g_Wh [2*G4*K_];     // fp16 Wih0, Wih1
__device__ float  g_ih [M_*G4];       // input projection (fp32)
__device__ __half g_y1h[M_*H_];       // layer-0 output (fp16)
__device__ __half g_hA [B_*H_];
__device__ __half g_hB [B_*H_];
__device__ unsigned g_bar;

// ---------------- ptx helpers ----------------
__device__ __forceinline__ void mma_f16(float* c, const uint32_t* a, const uint32_t* b) {
    asm volatile(
        "mma.sync.aligned.m16n8k16.row.col.f32.f16.f16.f32 "
        "{%0,%1,%2,%3}, {%4,%5,%6,%7}, {%8,%9}, {%0,%1,%2,%3};\n"
        : "+f"(c[0]), "+f"(c[1]), "+f"(c[2]), "+f"(c[3])
        : "r"(a[0]), "r"(a[1]), "r"(a[2]), "r"(a[3]), "r"(b[0]), "r"(b[1]));
}

__device__ __forceinline__ void ldsm_x4(uint32_t& r0, uint32_t& r1, uint32_t& r2, uint32_t& r3,
                                        uint32_t addr) {
    asm volatile("ldmatrix.sync.aligned.m8n8.x4.shared.b16 {%0,%1,%2,%3}, [%4];"
                 : "=r"(r0), "=r"(r1), "=r"(r2), "=r"(r3) : "r"(addr));
}

#define CP_ASYNC_CG(dst, src) \
    asm volatile("cp.async.cg.shared.global [%0], [%1], 16;\n" :: "r"(dst), "l"(src))
#define CP_COMMIT() asm volatile("cp.async.commit_group;\n" ::: "memory")
#define CP_WAIT(N)  asm volatile("cp.async.wait_group %0;\n" :: "n"(N) : "memory")

__device__ __forceinline__ float sig_f(float x) {
    return __fdividef(1.f, 1.f + __expf(-x));
}
__device__ __forceinline__ float tanh_f(float x) {
    float e = __expf(2.f * x);
    return 1.f - __fdividef(2.f, e + 1.f);
}

// ---------------- fp32 -> fp16 conversion ----------------
__global__ void round_half_kernel(const float* __restrict__ src, int n, int dsel) {
    __half* dst = (dsel == 0) ? g_xh : (g_Wh + (size_t)(dsel - 1) * (G4 * K_));
    int i4 = (blockIdx.x * blockDim.x + threadIdx.x) * 4;
    if (i4 < n) {
        float4 v = *(const float4*)(src + i4);
        *(__half2*)(dst + i4)     = __floats2half2_rn(v.x, v.y);
        *(__half2*)(dst + i4 + 2) = __floats2half2_rn(v.z, v.w);
    }
}

// ---------------- input projection GEMM (cp.async + ldmatrix) ----------------
#define BM 128
#define BN 128
#define BKH 32     // halves per k-iter
#define GSTR 40    // smem row stride in halves

__global__ __launch_bounds__(256, 1)
void gemm_ih_kernel(int asel, int woff, const float* __restrict__ bias) {
    const __half* A = asel ? g_y1h : g_xh;
    const __half* W = g_Wh + (size_t)woff * (G4 * K_);

    __shared__ __half As[2][BM * GSTR];
    __shared__ __half Bs[2][BM * GSTR];

    int tid  = threadIdx.x;
    int bm   = blockIdx.y * BM;
    int bn   = blockIdx.x * BN;
    int warp = tid >> 5, lane = tid & 31;
    int gid  = lane >> 2, tig = lane & 3;
    int wm   = (warp & 3) * 32;
    int wn   = (warp >> 2) * 64;

    uint32_t sa = (uint32_t)__cvta_generic_to_shared(&As[0][0]);
    uint32_t sb = (uint32_t)__cvta_generic_to_shared(&Bs[0][0]);
    const uint32_t STAGE = BM * GSTR * 2;   // bytes per stage

    // cp.async indexing: thread loads rows r0, r0+64; 16B chunk (tid&3)
    int r0   = tid >> 2;
    int gcol = (tid & 3) * 8;   // halves
    const __half* Ap = A + (size_t)(bm + r0) * K_ + gcol;
    const __half* Wp = W + (size_t)(bn + r0) * K_ + gcol;
    uint32_t da0 = sa + (uint32_t)(r0 * GSTR + gcol) * 2;
    uint32_t da1 = sa + (uint32_t)((r0 + 64) * GSTR + gcol) * 2;
    uint32_t db0 = sb + (uint32_t)(r0 * GSTR + gcol) * 2;
    uint32_t db1 = sb + (uint32_t)((r0 + 64) * GSTR + gcol) * 2;

    // ldmatrix lane offsets
    uint32_t a_off = (uint32_t)(((lane & 7) + ((lane >> 3) & 1) * 8) * GSTR + (lane >> 4) * 8) * 2;
    uint32_t b_off = (uint32_t)(((lane & 7) + ((lane >> 4) & 1) * 8) * GSTR + ((lane >> 3) & 1) * 8) * 2;

    float c[2][8][4];
#pragma unroll
    for (int i = 0; i < 2; i++)
#pragma unroll
        for (int j = 0; j < 8; j++)
#pragma unroll
            for (int q = 0; q < 4; q++) c[i][j][q] = 0.f;

    // prologue: stage 0
    CP_ASYNC_CG(da0, Ap);
    CP_ASYNC_CG(da1, Ap + (size_t)64 * K_);
    CP_ASYNC_CG(db0, Wp);
    CP_ASYNC_CG(db1, Wp + (size_t)64 * K_);
    CP_COMMIT();

    const int NIT = K_ / BKH;   // 32
    for (int it = 0; it < NIT; it++) {
        if (it + 1 < NIT) {
            int k = (it + 1) * BKH;
            uint32_t so = ((it + 1) & 1) * STAGE;
            CP_ASYNC_CG(da0 + so, Ap + k);
            CP_ASYNC_CG(da1 + so, Ap + (size_t)64 * K_ + k);
            CP_ASYNC_CG(db0 + so, Wp + k);
            CP_ASYNC_CG(db1 + so, Wp + (size_t)64 * K_ + k);
            CP_COMMIT();
            CP_WAIT(1);
        } else {
            CP_COMMIT();
            CP_WAIT(0);
        }
        __syncthreads();

        uint32_t sAs = sa + (it & 1) * STAGE;
        uint32_t sBs = sb + (it & 1) * STAGE;
#pragma unroll
        for (int ks = 0; ks < 2; ks++) {
            uint32_t af[2][4], bf[8][2];
#pragma unroll
            for (int mi = 0; mi < 2; mi++)
                ldsm_x4(af[mi][0], af[mi][1], af[mi][2], af[mi][3],
                        sAs + (uint32_t)((wm + mi * 16) * GSTR) * 2 + a_off + ks * 32);
#pragma unroll
            for (int nj = 0; nj < 4; nj++)
                ldsm_x4(bf[2 * nj][0], bf[2 * nj][1], bf[2 * nj + 1][0], bf[2 * nj + 1][1],
                        sBs + (uint32_t)((wn + nj * 16) * GSTR) * 2 + b_off + ks * 32);
#pragma unroll
            for (int mi = 0; mi < 2; mi++)
#pragma unroll
                for (int nj = 0; nj < 8; nj++)
                    mma_f16(c[mi][nj], af[mi], bf[nj]);
        }
        __syncthreads();
    }

#pragma unroll
    for (int mi = 0; mi < 2; mi++) {
#pragma unroll
        for (int nj = 0; nj < 8; nj++) {
            int m0 = bm + wm + mi * 16 + gid;
            int n0 = bn + wn + nj * 8 + 2 * tig;
            float b0v = bias[n0], b1v = bias[n0 + 1];
            size_t o = (size_t)m0 * G4 + n0;
            g_ih[o]                      = c[mi][nj][0] + b0v;
            g_ih[o + 1]                  = c[mi][nj][1] + b1v;
            g_ih[o + (size_t)8 * G4]     = c[mi][nj][2] + b0v;
            g_ih[o + (size_t)8 * G4 + 1] = c[mi][nj][3] + b1v;
        }
    }
}

// ---------------- zero h / barrier ----------------
__global__ void zero_state_kernel() {
    int i = blockIdx.x * blockDim.x + threadIdx.x;
    if (i < B_ * H_) {
        g_hA[i] = __float2half(0.f);
        g_hB[i] = __float2half(0.f);
    }
    if (i == 0) g_bar = 0u;
}

// ---------------- persistent recurrence kernel ----------------
// 8 warps = 2(m16) x 2(n16) x 2(k-half). Whole h staged per step in one shot.
#define WSTR 1032
#define HSTR 1032
#define PERSIST_SMEM ((32*WSTR + 32*HSTR) * 2 + 2 * 32 * 33 * 4)

__global__ __launch_bounds__(256, 1)
void lstm_persist_kernel(const float* __restrict__ Whh_raw, int outsel,
                         float* __restrict__ out_ext)
{
    extern __shared__ __half smh[];
    __half* Wsm = smh;                               // 32 x 1032 halves
    __half* Hsm = Wsm + 32 * WSTR;                   // 32 x 1032 halves
    float*  Ps  = (float*)(Hsm + 32 * HSTR);         // 2 x 32 x 33 floats

    int tid  = threadIdx.x;
    int warp = tid >> 5, lane = tid & 31;
    int gid  = lane >> 2, tig = lane & 3;
    int kh   = warp & 1;           // k-half
    int nj   = (warp >> 1) & 1;    // n16 tile
    int mi   = warp >> 2;          // m16 tile
    int j0   = blockIdx.x * 8;

    // ---- load Whh slice into SMEM once (fp16, gathered gate layout) ----
#pragma unroll 4
    for (int i = 0; i < 32; i++) {
        int idx = i * 256 + tid;
        int r   = idx >> 8;
        int c4  = idx & 255;
        int g   = r >> 3, jr = r & 7;
        const float4 v = *(const float4*)(Whh_raw + ((size_t)(g * H_ + j0 + jr)) * K_ + c4 * 4);
        *(__half2*)&Wsm[r * WSTR + c4 * 4]     = __floats2half2_rn(v.x, v.y);
        *(__half2*)&Wsm[r * WSTR + c4 * 4 + 2] = __floats2half2_rn(v.z, v.w);
    }

    uint32_t hs_base = (uint32_t)__cvta_generic_to_shared(Hsm);
    uint32_t ws_base = (uint32_t)__cvta_generic_to_shared(Wsm);
    uint32_t a_base = hs_base +
        (uint32_t)((mi * 16 + (lane & 7) + ((lane >> 3) & 1) * 8) * HSTR +
                   (lane >> 4) * 8 + kh * 512) * 2;
    uint32_t b_base = ws_base +
        (uint32_t)((nj * 16 + (lane & 7) + ((lane >> 4) & 1) * 8) * WSTR +
                   ((lane >> 3) & 1) * 8 + kh * 512) * 2;

    int hrow = tid >> 5;          // 0..7
    int hcol = (lane) * 8;        // halves
    int b    = tid >> 3;          // gate-math: batch
    int jj   = tid & 7;           // hidden col within slice
    float c_state = 0.f;
    float* Pk = Ps + kh * (32 * 33);

    __syncthreads();

    for (int t = 0; t < T_; t++) {
        const __half* hin  = (t & 1) ? g_hB : g_hA;
        __half*       hout = (t & 1) ? g_hA : g_hB;

        // prefetch ih gate operands
        size_t ihbase = ((size_t)(b * T_ + t)) * G4 + j0 + jj;
        float ih0 = __ldcs(&g_ih[ihbase]);
        float ih1 = __ldcs(&g_ih[ihbase + H_]);
        float ih2 = __ldcs(&g_ih[ihbase + 2 * H_]);
        float ih3 = __ldcs(&g_ih[ihbase + 3 * H_]);

        // ---- stage whole h into SMEM (one shot, full MLP) ----
        uint4 rv[16];
#pragma unroll
        for (int p = 0; p < 4; p++)
#pragma unroll
            for (int q = 0; q < 4; q++)
                rv[p * 4 + q] = __ldcg((const uint4*)(hin + (size_t)(hrow + 8 * p) * H_ +
                                                       q * 256 + hcol));
#pragma unroll
        for (int p = 0; p < 4; p++)
#pragma unroll
            for (int q = 0; q < 4; q++)
                *(uint4*)&Hsm[(hrow + 8 * p) * HSTR + q * 256 + hcol] = rv[p * 4 + q];
        __syncthreads();

        // ---- mma: warp computes m16 x n16 over its k-half ----
        float acc0[4] = {0.f, 0.f, 0.f, 0.f};
        float acc1[4] = {0.f, 0.f, 0.f, 0.f};
        uint32_t aaddr = a_base, baddr = b_base;
#pragma unroll
        for (int ks = 0; ks < 32; ks++) {
            uint32_t af[4], bl[2], bhh[2];
            ldsm_x4(af[0], af[1], af[2], af[3], aaddr);
            ldsm_x4(bl[0], bl[1], bhh[0], bhh[1], baddr);
            mma_f16(acc0, af, bl);
            mma_f16(acc1, af, bhh);
            aaddr += 32;
            baddr += 32;
        }

        // scatter partial pre-activations (per k-half buffer)
        {
            int m = mi * 16 + gid;
            int n = nj * 16 + 2 * tig;
            Pk[m * 33 + n]               = acc0[0];
            Pk[m * 33 + n + 1]           = acc0[1];
            Pk[(m + 8) * 33 + n]         = acc0[2];
            Pk[(m + 8) * 33 + n + 1]     = acc0[3];
            Pk[m * 33 + n + 8]           = acc1[0];
            Pk[m * 33 + n + 9]           = acc1[1];
            Pk[(m + 8) * 33 + n + 8]     = acc1[2];
            Pk[(m + 8) * 33 + n + 9]     = acc1[3];
        }
        __syncthreads();

        // gate math: one (b, jj) per thread
        {
            const float* P0 = Ps;
            const float* P1 = Ps + 32 * 33;
            float ipre = P0[b * 33 + jj]      + P1[b * 33 + jj]      + ih0;
            float fpre = P0[b * 33 + 8 + jj]  + P1[b * 33 + 8 + jj]  + ih1;
            float gpre = P0[b * 33 + 16 + jj] + P1[b * 33 + 16 + jj] + ih2;
            float opre = P0[b * 33 + 24 + jj] + P1[b * 33 + 24 + jj] + ih3;
            float iv = sig_f(ipre);
            float fv = sig_f(fpre);
            float gv = tanh_f(gpre);
            float ov = sig_f(opre);
            c_state = fv * c_state + iv * gv;
            float hv = ov * tanh_f(c_state);
            __half hr = __float2half_rn(hv);
            unsigned short hb16 = __half_as_ushort(hr);
            asm volatile("st.global.cg.u16 [%0], %1;"
                         :: "l"(hout + b * H_ + j0 + jj), "h"(hb16) : "memory");
            size_t oidx = ((size_t)(b * T_ + t)) * H_ + j0 + jj;
            if (outsel) out_ext[oidx] = hv;
            else        g_y1h[oidx]   = hr;
        }

        // ---- grid barrier ----
        __threadfence();
        __syncthreads();
        if (tid == 0) {
            atomicAdd(&g_bar, 1u);
            unsigned target = (unsigned)NCTA * (unsigned)(t + 1);
            unsigned v;
            do {
                asm volatile("ld.acquire.gpu.global.u32 %0, [%1];" : "=r"(v) : "l"(&g_bar));
            } while (v < target);
        }
        __syncthreads();
    }
}

// ---------------- launch ----------------
extern "C" void kernel_launch(void* const* d_in, const int* in_sizes, int n_in,
                              void* d_out, int out_size) {
    const float* x    = (const float*)d_in[0];
    const float* Wih0 = (const float*)d_in[1];
    const float* Whh0 = (const float*)d_in[2];
    const float* b0   = (const float*)d_in[3];
    const float* Wih1 = (const float*)d_in[4];
    const float* Whh1 = (const float*)d_in[5];
    const float* b1   = (const float*)d_in[6];
    float* out = (float*)d_out;

    static int smem_set = 0;
    if (!smem_set) {
        cudaFuncSetAttribute(lstm_persist_kernel,
                             cudaFuncAttributeMaxDynamicSharedMemorySize, PERSIST_SMEM);
        smem_set = 1;
    }

    const int nx = M_ * K_;
    const int nw = G4 * K_;
    round_half_kernel<<<(nx / 4 + 255) / 256, 256>>>(x,    nx, 0);
    round_half_kernel<<<(nw / 4 + 255) / 256, 256>>>(Wih0, nw, 1);
    round_half_kernel<<<(nw / 4 + 255) / 256, 256>>>(Wih1, nw, 2);

    dim3 ggrid(G4 / BN, M_ / BM);   // (32, 64)

    // layer 0
    gemm_ih_kernel<<<ggrid, 256>>>(0, 0, b0);
    zero_state_kernel<<<(B_ * H_ + 1023) / 1024, 1024>>>();
    lstm_persist_kernel<<<NCTA, 256, PERSIST_SMEM>>>(Whh0, 0, nullptr);

    // layer 1
    gemm_ih_kernel<<<ggrid, 256>>>(1, 1, b1);
    zero_state_kernel<<<(B_ * H_ + 1023) / 1024, 1024>>>();
    lstm_persist_kernel<<<NCTA, 256, PERSIST_SMEM>>>(Whh1, 1, out);
}